// round 13
// baseline (speedup 1.0000x reference)
#include <cuda_runtime.h>
#include <cuda_bf16.h>
#include <math.h>
#include <stdint.h>

#define NN 50000
#define NE 800000
#define IN_DIM 128
#define HID_DIM 256
#define OUT_DIM 64
#define SCAN_BLOCKS ((NN + 1023) / 1024)   // 49
#define MTILES ((NN + 127) / 128)          // 391

// ---------------- device scratch (no allocations allowed) ----------------
__device__ int   g_is64;
__device__ int   g_src[NE];
__device__ int   g_dst[NE];
__device__ int   g_deg[NN];
__device__ int   g_off[NN + 1];
__device__ int   g_cursor[NN];
__device__ int   g_csr_src[NE];
__device__ int   g_tilesum[SCAN_BLOCKS];
__device__ int   g_tileoff[SCAN_BLOCKS];
__device__ float g_mean[(size_t)NN * IN_DIM];
// split weight images, plain row-major [n][k] bf16
__device__ __align__(16) __nv_bfloat16 g_B1hi[HID_DIM * 256];   // [n=256][k=256]
__device__ __align__(16) __nv_bfloat16 g_B1lo[HID_DIM * 256];
__device__ __align__(16) __nv_bfloat16 g_B2hi[OUT_DIM * 256];   // [n=64][k=256]
__device__ __align__(16) __nv_bfloat16 g_B2lo[OUT_DIM * 256];

// ---------------- helpers ----------------
__device__ __forceinline__ uint32_t s2u(const void* p) {
    uint32_t a;
    asm("{ .reg .u64 t; cvta.to.shared.u64 t, %1; cvt.u32.u64 %0, t; }" : "=r"(a) : "l"(p));
    return a;
}
__device__ __forceinline__ void ldsm4(uint32_t* r, uint32_t addr) {
    asm volatile("ldmatrix.sync.aligned.m8n8.x4.shared.b16 {%0,%1,%2,%3}, [%4];"
        : "=r"(r[0]), "=r"(r[1]), "=r"(r[2]), "=r"(r[3]) : "r"(addr));
}
__device__ __forceinline__ void mma16816(float* d, const uint32_t* a, uint32_t b0, uint32_t b1) {
    asm volatile("mma.sync.aligned.m16n8k16.row.col.f32.bf16.bf16.f32 "
        "{%0,%1,%2,%3}, {%4,%5,%6,%7}, {%8,%9}, {%0,%1,%2,%3};"
        : "+f"(d[0]), "+f"(d[1]), "+f"(d[2]), "+f"(d[3])
        : "r"(a[0]), "r"(a[1]), "r"(a[2]), "r"(a[3]), "r"(b0), "r"(b1));
}
__device__ __forceinline__ uint32_t pack2(__nv_bfloat16 a, __nv_bfloat16 b) {
    union { __nv_bfloat16 h[2]; uint32_t u; } t;
    t.h[0] = a; t.h[1] = b;
    return t.u;
}

// ---------------- dtype probe: int64 (high words all 0) vs int32 ----------------
__global__ void detect_kernel(const unsigned int* __restrict__ ei32) {
    __shared__ int nz;
    if (threadIdx.x == 0) nz = 0;
    __syncthreads();
    int cnt = 0;
    for (int i = threadIdx.x; i < 4096; i += blockDim.x)
        if (ei32[2 * i + 1] != 0u) cnt++;
    atomicAdd(&nz, cnt);
    __syncthreads();
    if (threadIdx.x == 0) g_is64 = (nz == 0) ? 1 : 0;
}

__global__ void zero_deg_kernel() {
    int i = blockIdx.x * blockDim.x + threadIdx.x;
    if (i < NN) g_deg[i] = 0;
}

__global__ void convert_kernel(const void* __restrict__ ei) {
    int e = blockIdx.x * blockDim.x + threadIdx.x;
    if (e >= NE) return;
    int s, d;
    if (g_is64) {
        const long long* p = (const long long*)ei;
        s = (int)p[e];
        d = (int)p[NE + e];
    } else {
        const int* p = (const int*)ei;
        s = p[e];
        d = p[NE + e];
    }
    s = min(max(s, 0), NN - 1);
    d = min(max(d, 0), NN - 1);
    g_src[e] = s;
    g_dst[e] = d;
    atomicAdd(&g_deg[d], 1);
}

// ---------------- fast 3-phase scan ----------------
__global__ void __launch_bounds__(1024) scan1_kernel() {
    __shared__ int wsum[32];
    int b = blockIdx.x, t = threadIdx.x;
    int i = b * 1024 + t;
    int v = (i < NN) ? g_deg[i] : 0;
    int lane = t & 31, w = t >> 5;
    int x = v;
    #pragma unroll
    for (int o = 1; o < 32; o <<= 1) {
        int y = __shfl_up_sync(0xFFFFFFFFu, x, o);
        if (lane >= o) x += y;
    }
    if (lane == 31) wsum[w] = x;
    __syncthreads();
    if (w == 0) {
        int s = wsum[lane];
        #pragma unroll
        for (int o = 1; o < 32; o <<= 1) {
            int y = __shfl_up_sync(0xFFFFFFFFu, s, o);
            if (lane >= o) s += y;
        }
        wsum[lane] = s;
    }
    __syncthreads();
    int incl = x + (w > 0 ? wsum[w - 1] : 0);
    if (i < NN) g_off[i] = incl - v;
    if (t == 1023) g_tilesum[b] = incl;
}

__global__ void scan2_kernel() {
    int lane = threadIdx.x;
    int v0 = (lane < SCAN_BLOCKS) ? g_tilesum[lane] : 0;
    int v1 = (32 + lane < SCAN_BLOCKS) ? g_tilesum[32 + lane] : 0;
    int s0 = v0;
    #pragma unroll
    for (int o = 1; o < 32; o <<= 1) {
        int y = __shfl_up_sync(0xFFFFFFFFu, s0, o);
        if (lane >= o) s0 += y;
    }
    int tot0 = __shfl_sync(0xFFFFFFFFu, s0, 31);
    int s1 = v1;
    #pragma unroll
    for (int o = 1; o < 32; o <<= 1) {
        int y = __shfl_up_sync(0xFFFFFFFFu, s1, o);
        if (lane >= o) s1 += y;
    }
    s1 += tot0;
    if (lane < SCAN_BLOCKS) g_tileoff[lane] = s0 - v0;
    if (32 + lane < SCAN_BLOCKS) g_tileoff[32 + lane] = s1 - v1;
    int total = __shfl_sync(0xFFFFFFFFu, s1, SCAN_BLOCKS - 32 - 1);
    if (lane == 0) g_off[NN] = total;
}

__global__ void __launch_bounds__(1024) scan3_kernel() {
    int i = blockIdx.x * 1024 + threadIdx.x;
    if (i < NN) {
        int o = g_off[i] + g_tileoff[i >> 10];
        g_off[i] = o;
        g_cursor[i] = o;
    }
}

__global__ void scatter_kernel() {
    int e = blockIdx.x * blockDim.x + threadIdx.x;
    if (e < NE) {
        int d = g_dst[e];
        int s = g_src[e];
        int pos = atomicAdd(&g_cursor[d], 1);
        g_csr_src[pos] = s;
    }
}

// ---------------- mean aggregation (atomic-free, 1 node / 128-thread block) ----------------
__global__ void __launch_bounds__(128) agg_kernel(const float* __restrict__ x) {
    int node = blockIdx.x;
    int t = threadIdx.x;
    int beg = g_off[node];
    int end = g_off[node + 1];
    float acc = 0.f;
    for (int e = beg; e < end; e++) {
        int s = g_csr_src[e];
        acc += __ldg(&x[(size_t)s * IN_DIM + t]);
    }
    int d = end - beg;
    float inv = (d > 0) ? 1.0f / (float)d : 0.f;
    g_mean[(size_t)node * IN_DIM + t] = acc * inv;
}

// ---------------- weight prep: transpose + bf16 split (plain [n][k] layout) ----------------
__global__ void prep_b1(const float* __restrict__ Wl, const float* __restrict__ Wr) {
    int e = blockIdx.x * blockDim.x + threadIdx.x;   // 65536
    int n = e & 255, kg = e >> 8;
    float v = (kg < 128) ? Wl[kg * HID_DIM + n] : Wr[(kg - 128) * HID_DIM + n];
    __nv_bfloat16 hi = __float2bfloat16(v);
    __nv_bfloat16 lo = __float2bfloat16(v - __bfloat162float(hi));
    g_B1hi[n * 256 + kg] = hi;
    g_B1lo[n * 256 + kg] = lo;
}
__global__ void prep_b2(const float* __restrict__ Wout) {
    int e = blockIdx.x * blockDim.x + threadIdx.x;   // 16384
    int n = e & 63, kg = e >> 6;
    float v = Wout[kg * OUT_DIM + n];
    __nv_bfloat16 hi = __float2bfloat16(v);
    __nv_bfloat16 lo = __float2bfloat16(v - __bfloat162float(hi));
    g_B2hi[n * 256 + kg] = hi;
    g_B2lo[n * 256 + kg] = lo;
}

// ---------------- FUSED GEMM: out = elu([mean|x]@[Wl;Wr]+bl) @ Wout + bout ----------------
// grid = 391, 256 threads (8 warps, 4x2). A tile (128x256) staged ONCE as bf16 split in smem.
// Loop over 4 N-chunks of 64: gemm1 chunk -> ELU -> h chunk in smem -> gemm2 k-chunk accumulate.
#define FA_LD  264   // A smem stride in halves (528B = 33*16B, ldsm conflict-free)
#define FB1_LD 40    // B1 piece stride (80B = 5*16B)
#define FH_LD  72    // h buffer stride (144B = 9*16B)
#define FB2_LD 72

#define OFF_AH  0
#define OFF_AL  67584
#define OFF_B1H 135168
#define OFF_B1L 140288
#define OFF_HH  145408
#define OFF_HL  163840
#define OFF_B2H 182272
#define OFF_B2L 191488
#define FSMEM   200704

__global__ void __launch_bounds__(256, 1) fused_mma(const float* __restrict__ x,
                                                    const float* __restrict__ bl,
                                                    const float* __restrict__ bout,
                                                    float* __restrict__ out) {
    extern __shared__ char sm[];
    __nv_bfloat16* sAh  = (__nv_bfloat16*)(sm + OFF_AH);
    __nv_bfloat16* sAl  = (__nv_bfloat16*)(sm + OFF_AL);
    __nv_bfloat16* sB1h = (__nv_bfloat16*)(sm + OFF_B1H);
    __nv_bfloat16* sB1l = (__nv_bfloat16*)(sm + OFF_B1L);
    __nv_bfloat16* sHh  = (__nv_bfloat16*)(sm + OFF_HH);
    __nv_bfloat16* sHl  = (__nv_bfloat16*)(sm + OFF_HL);
    __nv_bfloat16* sB2h = (__nv_bfloat16*)(sm + OFF_B2H);
    __nv_bfloat16* sB2l = (__nv_bfloat16*)(sm + OFF_B2L);
    const uint32_t uAh = s2u(sAh), uAl = s2u(sAl);
    const uint32_t uB1h = s2u(sB1h), uB1l = s2u(sB1l);
    const uint32_t uHh = s2u(sHh), uHl = s2u(sHl);
    const uint32_t uB2h = s2u(sB2h), uB2l = s2u(sB2l);

    const int tid = threadIdx.x, lane = tid & 31, wid = tid >> 5;
    const int wr = wid & 3, wc = wid >> 2;          // 4x2 warp grid
    const int rowBase = blockIdx.x * 128;

    // ---- phase 1: A (virtual [mean|x]) -> bf16 split smem, read ONCE ----
    #pragma unroll
    for (int i = 0; i < 32; i++) {
        int idx = tid + i * 256;            // 0..8191 float4s
        int row = idx >> 6;                 // 0..127
        int c4  = idx & 63;                 // 0..63 (64 float4 per 256-col row)
        int grow = rowBase + row;
        float4 v = make_float4(0.f, 0.f, 0.f, 0.f);
        if (grow < NN)
            v = (c4 < 32)
                ? *(const float4*)&g_mean[(size_t)grow * IN_DIM + c4 * 4]
                : *(const float4*)&x[(size_t)grow * IN_DIM + (c4 - 32) * 4];
        float f[4] = {v.x, v.y, v.z, v.w};
        union { __nv_bfloat16 h[4]; uint2 u; } ph, pl;
        #pragma unroll
        for (int q = 0; q < 4; q++) {
            __nv_bfloat16 hi = __float2bfloat16(f[q]);
            ph.h[q] = hi;
            pl.h[q] = __float2bfloat16(f[q] - __bfloat162float(hi));
        }
        int addr = row * FA_LD + c4 * 4;
        *(uint2*)&sAh[addr] = ph.u;
        *(uint2*)&sAl[addr] = pl.u;
    }
    __syncthreads();

    float acc2[2][4][4];                    // persistent gemm2 accumulator (128x64 / 8 warps)
    #pragma unroll
    for (int i = 0; i < 2; i++)
        #pragma unroll
        for (int j = 0; j < 4; j++)
            #pragma unroll
            for (int q = 0; q < 4; q++) acc2[i][j][q] = 0.f;

    const int bsplit = tid >> 7, bidx = tid & 127;

    for (int nc = 0; nc < 4; nc++) {
        // ---- gemm1 chunk: (128x256) @ B1[nc*64..+64] -> acc1 (128x64) ----
        float acc1[2][4][4];
        #pragma unroll
        for (int i = 0; i < 2; i++)
            #pragma unroll
            for (int j = 0; j < 4; j++)
                #pragma unroll
                for (int q = 0; q < 4; q++) acc1[i][j][q] = 0.f;

        for (int kc = 0; kc < 8; kc++) {
            // stage B1 piece [64n][32k] split
            {
                int r = bidx >> 1, seg = bidx & 1;
                const __nv_bfloat16* srcp = (bsplit ? g_B1lo : g_B1hi)
                    + (nc * 64 + r) * 256 + kc * 32 + seg * 16;
                __nv_bfloat16* dst = (bsplit ? sB1l : sB1h) + r * FB1_LD + seg * 16;
                *(uint4*)(dst)     = *(const uint4*)(srcp);
                *(uint4*)(dst + 8) = *(const uint4*)(srcp + 8);
            }
            __syncthreads();

            #pragma unroll
            for (int ks = 0; ks < 2; ks++) {
                const int kcol = kc * 32 + ks * 16;
                uint32_t ah[2][4], al[2][4];
                #pragma unroll
                for (int mi = 0; mi < 2; mi++) {
                    int mrow = wr * 32 + mi * 16 + (lane & 15);
                    int acol = kcol + ((lane >> 4) << 3);
                    uint32_t off = (uint32_t)(mrow * FA_LD + acol) * 2;
                    ldsm4(ah[mi], uAh + off);
                    ldsm4(al[mi], uAl + off);
                }
                uint32_t bh[2][4], blr[2][4];
                #pragma unroll
                for (int p = 0; p < 2; p++) {
                    int nrow = wc * 32 + p * 16 + (lane & 7) + ((lane >> 4) << 3);
                    int bcol = ks * 16 + (((lane >> 3) & 1) << 3);
                    uint32_t off = (uint32_t)(nrow * FB1_LD + bcol) * 2;
                    ldsm4(bh[p],  uB1h + off);
                    ldsm4(blr[p], uB1l + off);
                }
                #pragma unroll
                for (int mi = 0; mi < 2; mi++)
                    #pragma unroll
                    for (int p = 0; p < 2; p++)
                        #pragma unroll
                        for (int q = 0; q < 2; q++) {
                            float* d = acc1[mi][p * 2 + q];
                            mma16816(d, ah[mi], bh[p][q * 2],  bh[p][q * 2 + 1]);
                            mma16816(d, ah[mi], blr[p][q * 2], blr[p][q * 2 + 1]);
                            mma16816(d, al[mi], bh[p][q * 2],  bh[p][q * 2 + 1]);
                        }
            }
            __syncthreads();
        }

        // ---- epilogue1: bias + ELU -> h chunk (bf16 split) in smem ----
        #pragma unroll
        for (int mi = 0; mi < 2; mi++)
            #pragma unroll
            for (int nj = 0; nj < 4; nj++) {
                int rloc = wr * 32 + mi * 16 + (lane >> 2);
                int c0 = wc * 32 + nj * 8 + 2 * (lane & 3);
                int gcol = nc * 64 + c0;
                float b0 = bl[gcol], b1 = bl[gcol + 1];
                #pragma unroll
                for (int half = 0; half < 2; half++) {
                    int rl = rloc + half * 8;
                    float v0 = acc1[mi][nj][half * 2]     + b0;
                    float v1 = acc1[mi][nj][half * 2 + 1] + b1;
                    v0 = (v0 > 0.f) ? v0 : expm1f(v0);
                    v1 = (v1 > 0.f) ? v1 : expm1f(v1);
                    __nv_bfloat16 h0 = __float2bfloat16(v0);
                    __nv_bfloat16 h1 = __float2bfloat16(v1);
                    __nv_bfloat16 l0 = __float2bfloat16(v0 - __bfloat162float(h0));
                    __nv_bfloat16 l1 = __float2bfloat16(v1 - __bfloat162float(h1));
                    *(uint32_t*)&sHh[rl * FH_LD + c0] = pack2(h0, h1);
                    *(uint32_t*)&sHl[rl * FH_LD + c0] = pack2(l0, l1);
                }
            }

        // ---- stage B2 piece: Wout k-rows [nc*64..+64), all 64 n, layout [n][64k] ----
        {
            int r = bidx >> 1, seg = bidx & 1;
            const __nv_bfloat16* srcp = (bsplit ? g_B2lo : g_B2hi) + r * 256 + nc * 64 + seg * 32;
            __nv_bfloat16* dst = (bsplit ? sB2l : sB2h) + r * FB2_LD + seg * 32;
            #pragma unroll
            for (int q = 0; q < 4; q++)
                *(uint4*)(dst + q * 8) = *(const uint4*)(srcp + q * 8);
        }
        __syncthreads();

        // ---- gemm2 partial: acc2 += h_chunk(128x64) @ B2piece(64x64) ----
        #pragma unroll
        for (int kc2 = 0; kc2 < 4; kc2++) {
            const int kcol = kc2 * 16;
            uint32_t ah[2][4], al[2][4];
            #pragma unroll
            for (int mi = 0; mi < 2; mi++) {
                int mrow = wr * 32 + mi * 16 + (lane & 15);
                int acol = kcol + ((lane >> 4) << 3);
                uint32_t off = (uint32_t)(mrow * FH_LD + acol) * 2;
                ldsm4(ah[mi], uHh + off);
                ldsm4(al[mi], uHl + off);
            }
            uint32_t bh[2][4], blr[2][4];
            #pragma unroll
            for (int p = 0; p < 2; p++) {
                int nrow = wc * 32 + p * 16 + (lane & 7) + ((lane >> 4) << 3);
                int bcol = kcol + (((lane >> 3) & 1) << 3);
                uint32_t off = (uint32_t)(nrow * FB2_LD + bcol) * 2;
                ldsm4(bh[p],  uB2h + off);
                ldsm4(blr[p], uB2l + off);
            }
            #pragma unroll
            for (int mi = 0; mi < 2; mi++)
                #pragma unroll
                for (int p = 0; p < 2; p++)
                    #pragma unroll
                    for (int q = 0; q < 2; q++) {
                        float* d = acc2[mi][p * 2 + q];
                        mma16816(d, ah[mi], bh[p][q * 2],  bh[p][q * 2 + 1]);
                        mma16816(d, ah[mi], blr[p][q * 2], blr[p][q * 2 + 1]);
                        mma16816(d, al[mi], bh[p][q * 2],  bh[p][q * 2 + 1]);
                    }
        }
        __syncthreads();   // h/B1/B2 buffers reused next nc
    }

    // ---- final epilogue: out = acc2 + bout ----
    #pragma unroll
    for (int mi = 0; mi < 2; mi++)
        #pragma unroll
        for (int nj = 0; nj < 4; nj++) {
            int r0 = rowBase + wr * 32 + mi * 16 + (lane >> 2);
            int c0 = wc * 32 + nj * 8 + 2 * (lane & 3);
            float b0 = bout[c0], b1 = bout[c0 + 1];
            #pragma unroll
            for (int half = 0; half < 2; half++) {
                int row = r0 + half * 8;
                if (row >= NN) continue;
                float2 v = make_float2(acc2[mi][nj][half * 2] + b0,
                                       acc2[mi][nj][half * 2 + 1] + b1);
                *(float2*)(out + (size_t)row * OUT_DIM + c0) = v;
            }
        }
}

// ---------------- launch ----------------
extern "C" void kernel_launch(void* const* d_in, const int* in_sizes, int n_in,
                              void* d_out, int out_size) {
    const float* x    = (const float*)d_in[0];
    const void*  ei   = d_in[1];
    const float* Wl   = (const float*)d_in[2];
    const float* bl   = (const float*)d_in[3];
    const float* Wr   = (const float*)d_in[4];
    const float* Wout = (const float*)d_in[5];
    const float* bout = (const float*)d_in[6];
    float* out = (float*)d_out;

    cudaFuncSetAttribute(fused_mma, cudaFuncAttributeMaxDynamicSharedMemorySize, FSMEM);

    detect_kernel<<<1, 256>>>((const unsigned int*)ei);
    zero_deg_kernel<<<(NN + 255) / 256, 256>>>();
    convert_kernel<<<(NE + 255) / 256, 256>>>(ei);
    scan1_kernel<<<SCAN_BLOCKS, 1024>>>();
    scan2_kernel<<<1, 32>>>();
    scan3_kernel<<<SCAN_BLOCKS, 1024>>>();
    scatter_kernel<<<(NE + 255) / 256, 256>>>();
    prep_b1<<<256, 256>>>(Wl, Wr);
    prep_b2<<<64, 256>>>(Wout);
    agg_kernel<<<NN, 128>>>(x);

    fused_mma<<<MTILES, 256, FSMEM>>>(x, bl, bout, out);
}

// round 16
// speedup vs baseline: 1.2647x; 1.2647x over previous
#include <cuda_runtime.h>
#include <cuda_bf16.h>
#include <math.h>
#include <stdint.h>

#define NN 50000
#define NE 800000
#define IN_DIM 128
#define HID_DIM 256
#define OUT_DIM 64
#define SCAN_BLOCKS ((NN + 1023) / 1024)   // 49
#define MTILES ((NN + 127) / 128)          // 391

// ---------------- device scratch (no allocations allowed) ----------------
__device__ int   g_is64;
__device__ int   g_src[NE];
__device__ int   g_dst[NE];
__device__ int   g_deg[NN];
__device__ int   g_off[NN + 1];      // tile-LOCAL exclusive offsets
__device__ int   g_cursor[NN];       // tile-LOCAL cursors
__device__ int   g_csr_src[NE];
__device__ int   g_tilesum[SCAN_BLOCKS];
__device__ int   g_tileoff[SCAN_BLOCKS];
__device__ float g_mean[(size_t)NN * IN_DIM];
// split weight images, plain row-major [n][k] bf16
__device__ __align__(16) __nv_bfloat16 g_B1hi[HID_DIM * 256];   // [n=256][k=256]
__device__ __align__(16) __nv_bfloat16 g_B1lo[HID_DIM * 256];
__device__ __align__(16) __nv_bfloat16 g_B2hi[OUT_DIM * 256];   // [n=64][k=256]
__device__ __align__(16) __nv_bfloat16 g_B2lo[OUT_DIM * 256];
// hidden activations, bf16 split
__device__ __align__(16) __nv_bfloat16 g_hhi[(size_t)NN * HID_DIM];
__device__ __align__(16) __nv_bfloat16 g_hlo[(size_t)NN * HID_DIM];

// ---------------- helpers ----------------
__device__ __forceinline__ uint32_t s2u(const void* p) {
    uint32_t a;
    asm("{ .reg .u64 t; cvta.to.shared.u64 t, %1; cvt.u32.u64 %0, t; }" : "=r"(a) : "l"(p));
    return a;
}
__device__ __forceinline__ void ldsm4(uint32_t* r, uint32_t addr) {
    asm volatile("ldmatrix.sync.aligned.m8n8.x4.shared.b16 {%0,%1,%2,%3}, [%4];"
        : "=r"(r[0]), "=r"(r[1]), "=r"(r[2]), "=r"(r[3]) : "r"(addr));
}
__device__ __forceinline__ void mma16816(float* d, const uint32_t* a, uint32_t b0, uint32_t b1) {
    asm volatile("mma.sync.aligned.m16n8k16.row.col.f32.bf16.bf16.f32 "
        "{%0,%1,%2,%3}, {%4,%5,%6,%7}, {%8,%9}, {%0,%1,%2,%3};"
        : "+f"(d[0]), "+f"(d[1]), "+f"(d[2]), "+f"(d[3])
        : "r"(a[0]), "r"(a[1]), "r"(a[2]), "r"(a[3]), "r"(b0), "r"(b1));
}
__device__ __forceinline__ uint32_t pack2(__nv_bfloat16 a, __nv_bfloat16 b) {
    union { __nv_bfloat16 h[2]; uint32_t u; } t;
    t.h[0] = a; t.h[1] = b;
    return t.u;
}

// ---------------- init: zero degrees + dtype probe (merged) ----------------
__global__ void init_kernel(const unsigned int* __restrict__ ei32) {
    int i = blockIdx.x * blockDim.x + threadIdx.x;
    if (i < NN) g_deg[i] = 0;
    if (blockIdx.x == 0) {
        __shared__ int nz;
        if (threadIdx.x == 0) nz = 0;
        __syncthreads();
        int cnt = 0;
        for (int k = threadIdx.x; k < 4096; k += blockDim.x)
            if (ei32[2 * k + 1] != 0u) cnt++;
        atomicAdd(&nz, cnt);
        __syncthreads();
        if (threadIdx.x == 0) g_is64 = (nz == 0) ? 1 : 0;
    }
}

__global__ void convert_kernel(const void* __restrict__ ei) {
    int e = blockIdx.x * blockDim.x + threadIdx.x;
    if (e >= NE) return;
    int s, d;
    if (g_is64) {
        const long long* p = (const long long*)ei;
        s = (int)p[e];
        d = (int)p[NE + e];
    } else {
        const int* p = (const int*)ei;
        s = p[e];
        d = p[NE + e];
    }
    s = min(max(s, 0), NN - 1);
    d = min(max(d, 0), NN - 1);
    g_src[e] = s;
    g_dst[e] = d;
    atomicAdd(&g_deg[d], 1);
}

// ---------------- 2-phase scan (tile-local offsets; no scan3) ----------------
__global__ void __launch_bounds__(1024) scan1_kernel() {
    __shared__ int wsum[32];
    int b = blockIdx.x, t = threadIdx.x;
    int i = b * 1024 + t;
    int v = (i < NN) ? g_deg[i] : 0;
    int lane = t & 31, w = t >> 5;
    int x = v;
    #pragma unroll
    for (int o = 1; o < 32; o <<= 1) {
        int y = __shfl_up_sync(0xFFFFFFFFu, x, o);
        if (lane >= o) x += y;
    }
    if (lane == 31) wsum[w] = x;
    __syncthreads();
    if (w == 0) {
        int s = wsum[lane];
        #pragma unroll
        for (int o = 1; o < 32; o <<= 1) {
            int y = __shfl_up_sync(0xFFFFFFFFu, s, o);
            if (lane >= o) s += y;
        }
        wsum[lane] = s;
    }
    __syncthreads();
    int incl = x + (w > 0 ? wsum[w - 1] : 0);
    int excl = incl - v;
    if (i <= NN) g_off[i] = excl;            // includes i == NN (local excl)
    if (i < NN)  g_cursor[i] = excl;
    if (t == 1023) g_tilesum[b] = incl;
}

__global__ void scan2_kernel() {
    int lane = threadIdx.x;
    int v0 = (lane < SCAN_BLOCKS) ? g_tilesum[lane] : 0;
    int v1 = (32 + lane < SCAN_BLOCKS) ? g_tilesum[32 + lane] : 0;
    int s0 = v0;
    #pragma unroll
    for (int o = 1; o < 32; o <<= 1) {
        int y = __shfl_up_sync(0xFFFFFFFFu, s0, o);
        if (lane >= o) s0 += y;
    }
    int tot0 = __shfl_sync(0xFFFFFFFFu, s0, 31);
    int s1 = v1;
    #pragma unroll
    for (int o = 1; o < 32; o <<= 1) {
        int y = __shfl_up_sync(0xFFFFFFFFu, s1, o);
        if (lane >= o) s1 += y;
    }
    s1 += tot0;
    if (lane < SCAN_BLOCKS) g_tileoff[lane] = s0 - v0;
    if (32 + lane < SCAN_BLOCKS) g_tileoff[32 + lane] = s1 - v1;
}

__global__ void scatter_kernel() {
    int e = blockIdx.x * blockDim.x + threadIdx.x;
    if (e < NE) {
        int d = g_dst[e];
        int s = g_src[e];
        int pos = atomicAdd(&g_cursor[d], 1) + g_tileoff[d >> 10];
        g_csr_src[pos] = s;
    }
}

// ---------------- mean aggregation: warp-per-node, float4 lanes, 4-edge MLP ----------------
__global__ void __launch_bounds__(256) agg_kernel(const float* __restrict__ x) {
    int gw = (blockIdx.x * 256 + threadIdx.x) >> 5;   // global warp id = node
    if (gw >= NN) return;
    int lane = threadIdx.x & 31;
    int beg = g_off[gw]     + g_tileoff[gw >> 10];
    int end = g_off[gw + 1] + g_tileoff[(gw + 1) >> 10];
    const float4* xp = (const float4*)x;
    float4 acc = make_float4(0.f, 0.f, 0.f, 0.f);
    int e = beg;
    for (; e + 4 <= end; e += 4) {
        int s0 = g_csr_src[e],     s1 = g_csr_src[e + 1];
        int s2 = g_csr_src[e + 2], s3 = g_csr_src[e + 3];
        float4 v0 = __ldg(&xp[(size_t)s0 * 32 + lane]);
        float4 v1 = __ldg(&xp[(size_t)s1 * 32 + lane]);
        float4 v2 = __ldg(&xp[(size_t)s2 * 32 + lane]);
        float4 v3 = __ldg(&xp[(size_t)s3 * 32 + lane]);
        acc.x += v0.x + v1.x + v2.x + v3.x;
        acc.y += v0.y + v1.y + v2.y + v3.y;
        acc.z += v0.z + v1.z + v2.z + v3.z;
        acc.w += v0.w + v1.w + v2.w + v3.w;
    }
    for (; e < end; e++) {
        int s = g_csr_src[e];
        float4 v = __ldg(&xp[(size_t)s * 32 + lane]);
        acc.x += v.x; acc.y += v.y; acc.z += v.z; acc.w += v.w;
    }
    int d = end - beg;
    float inv = (d > 0) ? 1.0f / (float)d : 0.f;
    acc.x *= inv; acc.y *= inv; acc.z *= inv; acc.w *= inv;
    ((float4*)g_mean)[(size_t)gw * 32 + lane] = acc;
}

// ---------------- weight prep: transpose + bf16 split (plain [n][k] layout) ----------------
__global__ void prep_b1(const float* __restrict__ Wl, const float* __restrict__ Wr) {
    int e = blockIdx.x * blockDim.x + threadIdx.x;   // 65536
    int n = e & 255, kg = e >> 8;
    float v = (kg < 128) ? Wl[kg * HID_DIM + n] : Wr[(kg - 128) * HID_DIM + n];
    __nv_bfloat16 hi = __float2bfloat16(v);
    __nv_bfloat16 lo = __float2bfloat16(v - __bfloat162float(hi));
    g_B1hi[n * 256 + kg] = hi;
    g_B1lo[n * 256 + kg] = lo;
}
__global__ void prep_b2(const float* __restrict__ Wout) {
    int e = blockIdx.x * blockDim.x + threadIdx.x;   // 16384
    int n = e & 63, kg = e >> 6;
    float v = Wout[kg * OUT_DIM + n];
    __nv_bfloat16 hi = __float2bfloat16(v);
    __nv_bfloat16 lo = __float2bfloat16(v - __bfloat162float(hi));
    g_B2hi[n * 256 + kg] = hi;
    g_B2lo[n * 256 + kg] = lo;
}

// ---------------- GEMM1 (HMMA): H = elu([mean|x] @ [W_l;W_r] + b_l) -> bf16 split ----------------
// grid (391, 4): BM=128, BN=64, K=256 in BK=32 chunks. 256 thr = 8 warps (4x2), warp 32x32.
#define LDA 40   // smem row stride in halves (80B: 16B-aligned, ldmatrix conflict-free)

__global__ void __launch_bounds__(256) gemm1_mma(const float* __restrict__ x,
                                                 const float* __restrict__ bl) {
    __shared__ __nv_bfloat16 sA[2][128 * LDA];   // [hi/lo][m][k]
    __shared__ __nv_bfloat16 sB[2][64 * LDA];    // [hi/lo][n][k]
    const int tid = threadIdx.x, lane = tid & 31, wid = tid >> 5;
    const int wr = wid & 3, wc = wid >> 2;
    const int rowBase = blockIdx.x * 128;
    const int colBase = blockIdx.y * 64;
    const uint32_t sA0 = s2u(&sA[0][0]), sA1 = s2u(&sA[1][0]);
    const uint32_t sB0 = s2u(&sB[0][0]), sB1 = s2u(&sB[1][0]);

    float acc[2][4][4];
    #pragma unroll
    for (int i = 0; i < 2; i++)
        #pragma unroll
        for (int j = 0; j < 4; j++)
            #pragma unroll
            for (int q = 0; q < 4; q++) acc[i][j][q] = 0.f;

    const int arow = tid >> 1, aseg = tid & 1;          // A staging: row, 16-col segment
    const int grow = rowBase + arow;
    const bool okrow = grow < NN;
    const int bsplit = tid >> 7, bidx = tid & 127;      // B staging
    const int brow = bidx >> 1, bseg = bidx & 1;

    for (int kc = 0; kc < 8; kc++) {
        // ---- stage A: fp32 -> bf16 split, 16 floats per thread ----
        {
            const float* src = (kc < 4)
                ? g_mean + (size_t)grow * IN_DIM + kc * 32 + aseg * 16
                : x      + (size_t)grow * IN_DIM + (kc - 4) * 32 + aseg * 16;
            float f[16];
            if (okrow) {
                #pragma unroll
                for (int q = 0; q < 4; q++) {
                    float4 v = *(const float4*)(src + q * 4);
                    f[q * 4] = v.x; f[q * 4 + 1] = v.y; f[q * 4 + 2] = v.z; f[q * 4 + 3] = v.w;
                }
            } else {
                #pragma unroll
                for (int q = 0; q < 16; q++) f[q] = 0.f;
            }
            union { __nv_bfloat16 h[16]; uint4 u[2]; } ph, pl;
            #pragma unroll
            for (int q = 0; q < 16; q++) {
                __nv_bfloat16 hi = __float2bfloat16(f[q]);
                ph.h[q] = hi;
                pl.h[q] = __float2bfloat16(f[q] - __bfloat162float(hi));
            }
            __nv_bfloat16* dh = &sA[0][arow * LDA + aseg * 16];
            __nv_bfloat16* dl = &sA[1][arow * LDA + aseg * 16];
            *(uint4*)(dh) = ph.u[0]; *(uint4*)(dh + 8) = ph.u[1];
            *(uint4*)(dl) = pl.u[0]; *(uint4*)(dl + 8) = pl.u[1];
        }
        // ---- stage B: copy split image rows [colBase+brow], cols kc*32+bseg*16 ----
        {
            const __nv_bfloat16* srcp = (bsplit == 0 ? g_B1hi : g_B1lo)
                + (colBase + brow) * 256 + kc * 32 + bseg * 16;
            __nv_bfloat16* dst = &sB[bsplit][brow * LDA + bseg * 16];
            *(uint4*)(dst)     = *(const uint4*)(srcp);
            *(uint4*)(dst + 8) = *(const uint4*)(srcp + 8);
        }
        __syncthreads();

        // ---- compute: 2 k16 steps ----
        #pragma unroll
        for (int ks = 0; ks < 2; ks++) {
            const int kcol = ks * 16;
            uint32_t ah[2][4], al[2][4];
            #pragma unroll
            for (int mi = 0; mi < 2; mi++) {
                int mrow = wr * 32 + mi * 16 + (lane & 15);
                int coff = kcol + ((lane >> 4) << 3);
                uint32_t byteoff = (uint32_t)(mrow * LDA + coff) * 2;
                ldsm4(ah[mi], sA0 + byteoff);
                ldsm4(al[mi], sA1 + byteoff);
            }
            uint32_t bh[2][4], blr[2][4];
            #pragma unroll
            for (int p = 0; p < 2; p++) {
                int nrow = wc * 32 + p * 16 + (lane & 7) + ((lane >> 4) << 3);
                int coff = kcol + (((lane >> 3) & 1) << 3);
                uint32_t byteoff = (uint32_t)(nrow * LDA + coff) * 2;
                ldsm4(bh[p],  sB0 + byteoff);
                ldsm4(blr[p], sB1 + byteoff);
            }
            #pragma unroll
            for (int mi = 0; mi < 2; mi++)
                #pragma unroll
                for (int p = 0; p < 2; p++)
                    #pragma unroll
                    for (int q = 0; q < 2; q++) {
                        float* d = acc[mi][p * 2 + q];
                        mma16816(d, ah[mi], bh[p][q * 2],  bh[p][q * 2 + 1]);
                        mma16816(d, ah[mi], blr[p][q * 2], blr[p][q * 2 + 1]);
                        mma16816(d, al[mi], bh[p][q * 2],  bh[p][q * 2 + 1]);
                    }
        }
        __syncthreads();
    }

    // ---- epilogue: bias + ELU -> bf16 split store ----
    #pragma unroll
    for (int mi = 0; mi < 2; mi++)
        #pragma unroll
        for (int nj = 0; nj < 4; nj++) {
            int r0 = rowBase + wr * 32 + mi * 16 + (lane >> 2);
            int c0 = colBase + wc * 32 + nj * 8 + 2 * (lane & 3);
            float b0 = bl[c0], b1 = bl[c0 + 1];
            #pragma unroll
            for (int half = 0; half < 2; half++) {
                int row = r0 + half * 8;
                if (row >= NN) continue;
                float v0 = acc[mi][nj][half * 2]     + b0;
                float v1 = acc[mi][nj][half * 2 + 1] + b1;
                v0 = (v0 > 0.f) ? v0 : expm1f(v0);
                v1 = (v1 > 0.f) ? v1 : expm1f(v1);
                __nv_bfloat16 h0 = __float2bfloat16(v0);
                __nv_bfloat16 h1 = __float2bfloat16(v1);
                __nv_bfloat16 l0 = __float2bfloat16(v0 - __bfloat162float(h0));
                __nv_bfloat16 l1 = __float2bfloat16(v1 - __bfloat162float(h1));
                *(uint32_t*)(g_hhi + (size_t)row * HID_DIM + c0) = pack2(h0, h1);
                *(uint32_t*)(g_hlo + (size_t)row * HID_DIM + c0) = pack2(l0, l1);
            }
        }
}

// ---------------- GEMM2 (HMMA): out = H @ W_out + b_out ----------------
// grid (391): BM=128, BN=64, K=256. Same skeleton; A is already bf16 split.
__global__ void __launch_bounds__(256) gemm2_mma(const float* __restrict__ bout,
                                                 float* __restrict__ out) {
    __shared__ __nv_bfloat16 sA[2][128 * LDA];
    __shared__ __nv_bfloat16 sB[2][64 * LDA];
    const int tid = threadIdx.x, lane = tid & 31, wid = tid >> 5;
    const int wr = wid & 3, wc = wid >> 2;
    const int rowBase = blockIdx.x * 128;
    const uint32_t sA0 = s2u(&sA[0][0]), sA1 = s2u(&sA[1][0]);
    const uint32_t sB0 = s2u(&sB[0][0]), sB1 = s2u(&sB[1][0]);

    float acc[2][4][4];
    #pragma unroll
    for (int i = 0; i < 2; i++)
        #pragma unroll
        for (int j = 0; j < 4; j++)
            #pragma unroll
            for (int q = 0; q < 4; q++) acc[i][j][q] = 0.f;

    const int arow = tid >> 1, aseg = tid & 1;
    const int grow = rowBase + arow;
    const bool okrow = grow < NN;
    const int bsplit = tid >> 7, bidx = tid & 127;
    const int brow = bidx >> 1, bseg = bidx & 1;
    const uint4 z4 = make_uint4(0, 0, 0, 0);

    for (int kc = 0; kc < 8; kc++) {
        // stage A (copy bf16 split)
        {
            const __nv_bfloat16* shp = g_hhi + (size_t)grow * HID_DIM + kc * 32 + aseg * 16;
            const __nv_bfloat16* slp = g_hlo + (size_t)grow * HID_DIM + kc * 32 + aseg * 16;
            __nv_bfloat16* dh = &sA[0][arow * LDA + aseg * 16];
            __nv_bfloat16* dl = &sA[1][arow * LDA + aseg * 16];
            *(uint4*)(dh)     = okrow ? *(const uint4*)(shp)     : z4;
            *(uint4*)(dh + 8) = okrow ? *(const uint4*)(shp + 8) : z4;
            *(uint4*)(dl)     = okrow ? *(const uint4*)(slp)     : z4;
            *(uint4*)(dl + 8) = okrow ? *(const uint4*)(slp + 8) : z4;
        }
        // stage B
        {
            const __nv_bfloat16* srcp = (bsplit == 0 ? g_B2hi : g_B2lo)
                + brow * 256 + kc * 32 + bseg * 16;
            __nv_bfloat16* dst = &sB[bsplit][brow * LDA + bseg * 16];
            *(uint4*)(dst)     = *(const uint4*)(srcp);
            *(uint4*)(dst + 8) = *(const uint4*)(srcp + 8);
        }
        __syncthreads();

        #pragma unroll
        for (int ks = 0; ks < 2; ks++) {
            const int kcol = ks * 16;
            uint32_t ah[2][4], al[2][4];
            #pragma unroll
            for (int mi = 0; mi < 2; mi++) {
                int mrow = wr * 32 + mi * 16 + (lane & 15);
                int coff = kcol + ((lane >> 4) << 3);
                uint32_t byteoff = (uint32_t)(mrow * LDA + coff) * 2;
                ldsm4(ah[mi], sA0 + byteoff);
                ldsm4(al[mi], sA1 + byteoff);
            }
            uint32_t bh[2][4], blr[2][4];
            #pragma unroll
            for (int p = 0; p < 2; p++) {
                int nrow = wc * 32 + p * 16 + (lane & 7) + ((lane >> 4) << 3);
                int coff = kcol + (((lane >> 3) & 1) << 3);
                uint32_t byteoff = (uint32_t)(nrow * LDA + coff) * 2;
                ldsm4(bh[p],  sB0 + byteoff);
                ldsm4(blr[p], sB1 + byteoff);
            }
            #pragma unroll
            for (int mi = 0; mi < 2; mi++)
                #pragma unroll
                for (int p = 0; p < 2; p++)
                    #pragma unroll
                    for (int q = 0; q < 2; q++) {
                        float* d = acc[mi][p * 2 + q];
                        mma16816(d, ah[mi], bh[p][q * 2],  bh[p][q * 2 + 1]);
                        mma16816(d, ah[mi], blr[p][q * 2], blr[p][q * 2 + 1]);
                        mma16816(d, al[mi], bh[p][q * 2],  bh[p][q * 2 + 1]);
                    }
        }
        __syncthreads();
    }

    // epilogue: + bias, fp32 float2 stores
    #pragma unroll
    for (int mi = 0; mi < 2; mi++)
        #pragma unroll
        for (int nj = 0; nj < 4; nj++) {
            int r0 = rowBase + wr * 32 + mi * 16 + (lane >> 2);
            int c0 = wc * 32 + nj * 8 + 2 * (lane & 3);
            float b0 = bout[c0], b1 = bout[c0 + 1];
            #pragma unroll
            for (int half = 0; half < 2; half++) {
                int row = r0 + half * 8;
                if (row >= NN) continue;
                float2 v = make_float2(acc[mi][nj][half * 2] + b0,
                                       acc[mi][nj][half * 2 + 1] + b1);
                *(float2*)(out + (size_t)row * OUT_DIM + c0) = v;
            }
        }
}

// ---------------- launch ----------------
extern "C" void kernel_launch(void* const* d_in, const int* in_sizes, int n_in,
                              void* d_out, int out_size) {
    const float* x    = (const float*)d_in[0];
    const void*  ei   = d_in[1];
    const float* Wl   = (const float*)d_in[2];
    const float* bl   = (const float*)d_in[3];
    const float* Wr   = (const float*)d_in[4];
    const float* Wout = (const float*)d_in[5];
    const float* bout = (const float*)d_in[6];
    float* out = (float*)d_out;

    init_kernel<<<(NN + 255) / 256, 256>>>((const unsigned int*)ei);
    convert_kernel<<<(NE + 255) / 256, 256>>>(ei);
    scan1_kernel<<<SCAN_BLOCKS, 1024>>>();
    scan2_kernel<<<1, 32>>>();
    scatter_kernel<<<(NE + 255) / 256, 256>>>();
    prep_b1<<<256, 256>>>(Wl, Wr);
    prep_b2<<<64, 256>>>(Wout);
    agg_kernel<<<(NN * 32 + 255) / 256, 256>>>(x);

    dim3 g1(MTILES, 4);
    gemm1_mma<<<g1, 256>>>(x, bl);
    gemm2_mma<<<MTILES, 256>>>(bout, out);
}

// round 17
// speedup vs baseline: 1.3008x; 1.0285x over previous
#include <cuda_runtime.h>
#include <cuda_bf16.h>
#include <math.h>
#include <stdint.h>

#define NN 50000
#define NE 800000
#define IN_DIM 128
#define HID_DIM 256
#define OUT_DIM 64
#define SCAN_BLOCKS ((NN + 1023) / 1024)   // 49
#define MTILES ((NN + 127) / 128)          // 391

// ---------------- device scratch (no allocations allowed) ----------------
__device__ int   g_is64;
__device__ int   g_scan_ticket;
__device__ int   g_deg[NN];
__device__ int   g_off[NN + 1];      // tile-LOCAL exclusive offsets
__device__ int   g_cursor[NN];       // tile-LOCAL cursors
__device__ int   g_src[NE];
__device__ int   g_dst[NE];
__device__ int   g_csr_src[NE];
__device__ int   g_tilesum[SCAN_BLOCKS];
__device__ int   g_tileoff[SCAN_BLOCKS];
__device__ float g_mean[(size_t)NN * IN_DIM];
// split weight images, plain row-major [n][k] bf16
__device__ __align__(16) __nv_bfloat16 g_B1hi[HID_DIM * 256];   // [n=256][k=256]
__device__ __align__(16) __nv_bfloat16 g_B1lo[HID_DIM * 256];
__device__ __align__(16) __nv_bfloat16 g_B2hi[OUT_DIM * 256];   // [n=64][k=256]
__device__ __align__(16) __nv_bfloat16 g_B2lo[OUT_DIM * 256];
// hidden activations, bf16 split
__device__ __align__(16) __nv_bfloat16 g_hhi[(size_t)NN * HID_DIM];
__device__ __align__(16) __nv_bfloat16 g_hlo[(size_t)NN * HID_DIM];

// ---------------- helpers ----------------
__device__ __forceinline__ uint32_t s2u(const void* p) {
    uint32_t a;
    asm("{ .reg .u64 t; cvta.to.shared.u64 t, %1; cvt.u32.u64 %0, t; }" : "=r"(a) : "l"(p));
    return a;
}
__device__ __forceinline__ void ldsm4(uint32_t* r, uint32_t addr) {
    asm volatile("ldmatrix.sync.aligned.m8n8.x4.shared.b16 {%0,%1,%2,%3}, [%4];"
        : "=r"(r[0]), "=r"(r[1]), "=r"(r[2]), "=r"(r[3]) : "r"(addr));
}
__device__ __forceinline__ void mma16816(float* d, const uint32_t* a, uint32_t b0, uint32_t b1) {
    asm volatile("mma.sync.aligned.m16n8k16.row.col.f32.bf16.bf16.f32 "
        "{%0,%1,%2,%3}, {%4,%5,%6,%7}, {%8,%9}, {%0,%1,%2,%3};"
        : "+f"(d[0]), "+f"(d[1]), "+f"(d[2]), "+f"(d[3])
        : "r"(a[0]), "r"(a[1]), "r"(a[2]), "r"(a[3]), "r"(b0), "r"(b1));
}
__device__ __forceinline__ uint32_t pack2(__nv_bfloat16 a, __nv_bfloat16 b) {
    union { __nv_bfloat16 h[2]; uint32_t u; } t;
    t.h[0] = a; t.h[1] = b;
    return t.u;
}

// ---------------- setup: zero deg + ticket, dtype probe, weight split (merged) ----------------
// grid 256 x 256 threads = 65536
__global__ void setup_kernel(const unsigned int* __restrict__ ei32,
                             const float* __restrict__ Wl,
                             const float* __restrict__ Wr,
                             const float* __restrict__ Wout) {
    int e = blockIdx.x * blockDim.x + threadIdx.x;   // 0..65535
    if (e == 0) g_scan_ticket = 0;
    if (e < NN) g_deg[e] = 0;
    // B1 split: all 65536 elements
    {
        int n = e & 255, kg = e >> 8;
        float v = (kg < 128) ? Wl[kg * HID_DIM + n] : Wr[(kg - 128) * HID_DIM + n];
        __nv_bfloat16 hi = __float2bfloat16(v);
        __nv_bfloat16 lo = __float2bfloat16(v - __bfloat162float(hi));
        g_B1hi[n * 256 + kg] = hi;
        g_B1lo[n * 256 + kg] = lo;
    }
    // B2 split: first 16384 elements
    if (e < 16384) {
        int n = e & 63, kg = e >> 6;
        float v = Wout[kg * OUT_DIM + n];
        __nv_bfloat16 hi = __float2bfloat16(v);
        __nv_bfloat16 lo = __float2bfloat16(v - __bfloat162float(hi));
        g_B2hi[n * 256 + kg] = hi;
        g_B2lo[n * 256 + kg] = lo;
    }
    // dtype probe: block 0
    if (blockIdx.x == 0) {
        __shared__ int nz;
        if (threadIdx.x == 0) nz = 0;
        __syncthreads();
        int cnt = 0;
        for (int k = threadIdx.x; k < 4096; k += blockDim.x)
            if (ei32[2 * k + 1] != 0u) cnt++;
        atomicAdd(&nz, cnt);
        __syncthreads();
        if (threadIdx.x == 0) g_is64 = (nz == 0) ? 1 : 0;
    }
}

__global__ void convert_kernel(const void* __restrict__ ei) {
    int e = blockIdx.x * blockDim.x + threadIdx.x;
    if (e >= NE) return;
    int s, d;
    if (g_is64) {
        const long long* p = (const long long*)ei;
        s = (int)p[e];
        d = (int)p[NE + e];
    } else {
        const int* p = (const int*)ei;
        s = p[e];
        d = p[NE + e];
    }
    s = min(max(s, 0), NN - 1);
    d = min(max(d, 0), NN - 1);
    g_src[e] = s;
    g_dst[e] = d;
    atomicAdd(&g_deg[d], 1);
}

// ---------------- single-launch scan: per-tile local scan + last-block tile-sum scan ----------------
__global__ void __launch_bounds__(1024) scan_kernel() {
    __shared__ int wsum[32];
    __shared__ int is_last;
    int b = blockIdx.x, t = threadIdx.x;
    int i = b * 1024 + t;
    int v = (i < NN) ? g_deg[i] : 0;
    int lane = t & 31, w = t >> 5;
    int x = v;
    #pragma unroll
    for (int o = 1; o < 32; o <<= 1) {
        int y = __shfl_up_sync(0xFFFFFFFFu, x, o);
        if (lane >= o) x += y;
    }
    if (lane == 31) wsum[w] = x;
    __syncthreads();
    if (w == 0) {
        int s = wsum[lane];
        #pragma unroll
        for (int o = 1; o < 32; o <<= 1) {
            int y = __shfl_up_sync(0xFFFFFFFFu, s, o);
            if (lane >= o) s += y;
        }
        wsum[lane] = s;
    }
    __syncthreads();
    int incl = x + (w > 0 ? wsum[w - 1] : 0);
    int excl = incl - v;
    if (i <= NN) g_off[i] = excl;            // includes i == NN (local excl)
    if (i < NN)  g_cursor[i] = excl;
    if (t == 1023) g_tilesum[b] = incl;

    // last-arriving block scans the 49 tile sums
    __threadfence();
    __syncthreads();
    if (t == 0) {
        int ticket = atomicAdd(&g_scan_ticket, 1);
        is_last = (ticket == SCAN_BLOCKS - 1) ? 1 : 0;
    }
    __syncthreads();
    if (is_last && w == 0) {
        int v0 = (lane < SCAN_BLOCKS) ? g_tilesum[lane] : 0;
        int v1 = (32 + lane < SCAN_BLOCKS) ? g_tilesum[32 + lane] : 0;
        int s0 = v0;
        #pragma unroll
        for (int o = 1; o < 32; o <<= 1) {
            int y = __shfl_up_sync(0xFFFFFFFFu, s0, o);
            if (lane >= o) s0 += y;
        }
        int tot0 = __shfl_sync(0xFFFFFFFFu, s0, 31);
        int s1 = v1;
        #pragma unroll
        for (int o = 1; o < 32; o <<= 1) {
            int y = __shfl_up_sync(0xFFFFFFFFu, s1, o);
            if (lane >= o) s1 += y;
        }
        s1 += tot0;
        if (lane < SCAN_BLOCKS) g_tileoff[lane] = s0 - v0;
        if (32 + lane < SCAN_BLOCKS) g_tileoff[32 + lane] = s1 - v1;
        __threadfence();
    }
}

__global__ void scatter_kernel() {
    int e = blockIdx.x * blockDim.x + threadIdx.x;
    if (e < NE) {
        int d = g_dst[e];
        int s = g_src[e];
        int pos = atomicAdd(&g_cursor[d], 1) + g_tileoff[d >> 10];
        g_csr_src[pos] = s;
    }
}

// ---------------- mean aggregation: warp-per-node, float4 lanes, 4-edge MLP ----------------
__global__ void __launch_bounds__(256) agg_kernel(const float* __restrict__ x) {
    int gw = (blockIdx.x * 256 + threadIdx.x) >> 5;   // global warp id = node
    if (gw >= NN) return;
    int lane = threadIdx.x & 31;
    int beg = g_off[gw]     + g_tileoff[gw >> 10];
    int end = g_off[gw + 1] + g_tileoff[(gw + 1) >> 10];
    const float4* xp = (const float4*)x;
    float4 acc = make_float4(0.f, 0.f, 0.f, 0.f);
    int e = beg;
    for (; e + 4 <= end; e += 4) {
        int s0 = g_csr_src[e],     s1 = g_csr_src[e + 1];
        int s2 = g_csr_src[e + 2], s3 = g_csr_src[e + 3];
        float4 v0 = __ldg(&xp[(size_t)s0 * 32 + lane]);
        float4 v1 = __ldg(&xp[(size_t)s1 * 32 + lane]);
        float4 v2 = __ldg(&xp[(size_t)s2 * 32 + lane]);
        float4 v3 = __ldg(&xp[(size_t)s3 * 32 + lane]);
        acc.x += v0.x + v1.x + v2.x + v3.x;
        acc.y += v0.y + v1.y + v2.y + v3.y;
        acc.z += v0.z + v1.z + v2.z + v3.z;
        acc.w += v0.w + v1.w + v2.w + v3.w;
    }
    for (; e < end; e++) {
        int s = g_csr_src[e];
        float4 v = __ldg(&xp[(size_t)s * 32 + lane]);
        acc.x += v.x; acc.y += v.y; acc.z += v.z; acc.w += v.w;
    }
    int d = end - beg;
    float inv = (d > 0) ? 1.0f / (float)d : 0.f;
    acc.x *= inv; acc.y *= inv; acc.z *= inv; acc.w *= inv;
    ((float4*)g_mean)[(size_t)gw * 32 + lane] = acc;
}

// ---------------- GEMM1 (HMMA): H = elu([mean|x] @ [W_l;W_r] + b_l) -> bf16 split ----------------
// grid (391, 4): BM=128, BN=64, K=256 in BK=32 chunks. 256 thr = 8 warps (4x2), warp 32x32.
#define LDA 40   // smem row stride in halves (80B: 16B-aligned, ldmatrix conflict-free)

__global__ void __launch_bounds__(256) gemm1_mma(const float* __restrict__ x,
                                                 const float* __restrict__ bl) {
    __shared__ __nv_bfloat16 sA[2][128 * LDA];   // [hi/lo][m][k]
    __shared__ __nv_bfloat16 sB[2][64 * LDA];    // [hi/lo][n][k]
    const int tid = threadIdx.x, lane = tid & 31, wid = tid >> 5;
    const int wr = wid & 3, wc = wid >> 2;
    const int rowBase = blockIdx.x * 128;
    const int colBase = blockIdx.y * 64;
    const uint32_t sA0 = s2u(&sA[0][0]), sA1 = s2u(&sA[1][0]);
    const uint32_t sB0 = s2u(&sB[0][0]), sB1 = s2u(&sB[1][0]);

    float acc[2][4][4];
    #pragma unroll
    for (int i = 0; i < 2; i++)
        #pragma unroll
        for (int j = 0; j < 4; j++)
            #pragma unroll
            for (int q = 0; q < 4; q++) acc[i][j][q] = 0.f;

    const int arow = tid >> 1, aseg = tid & 1;          // A staging: row, 16-col segment
    const int grow = rowBase + arow;
    const bool okrow = grow < NN;
    const int bsplit = tid >> 7, bidx = tid & 127;      // B staging
    const int brow = bidx >> 1, bseg = bidx & 1;

    for (int kc = 0; kc < 8; kc++) {
        // ---- stage A: fp32 -> bf16 split, 16 floats per thread ----
        {
            const float* src = (kc < 4)
                ? g_mean + (size_t)grow * IN_DIM + kc * 32 + aseg * 16
                : x      + (size_t)grow * IN_DIM + (kc - 4) * 32 + aseg * 16;
            float f[16];
            if (okrow) {
                #pragma unroll
                for (int q = 0; q < 4; q++) {
                    float4 v = *(const float4*)(src + q * 4);
                    f[q * 4] = v.x; f[q * 4 + 1] = v.y; f[q * 4 + 2] = v.z; f[q * 4 + 3] = v.w;
                }
            } else {
                #pragma unroll
                for (int q = 0; q < 16; q++) f[q] = 0.f;
            }
            union { __nv_bfloat16 h[16]; uint4 u[2]; } ph, pl;
            #pragma unroll
            for (int q = 0; q < 16; q++) {
                __nv_bfloat16 hi = __float2bfloat16(f[q]);
                ph.h[q] = hi;
                pl.h[q] = __float2bfloat16(f[q] - __bfloat162float(hi));
            }
            __nv_bfloat16* dh = &sA[0][arow * LDA + aseg * 16];
            __nv_bfloat16* dl = &sA[1][arow * LDA + aseg * 16];
            *(uint4*)(dh) = ph.u[0]; *(uint4*)(dh + 8) = ph.u[1];
            *(uint4*)(dl) = pl.u[0]; *(uint4*)(dl + 8) = pl.u[1];
        }
        // ---- stage B: copy split image rows [colBase+brow], cols kc*32+bseg*16 ----
        {
            const __nv_bfloat16* srcp = (bsplit == 0 ? g_B1hi : g_B1lo)
                + (colBase + brow) * 256 + kc * 32 + bseg * 16;
            __nv_bfloat16* dst = &sB[bsplit][brow * LDA + bseg * 16];
            *(uint4*)(dst)     = *(const uint4*)(srcp);
            *(uint4*)(dst + 8) = *(const uint4*)(srcp + 8);
        }
        __syncthreads();

        // ---- compute: 2 k16 steps ----
        #pragma unroll
        for (int ks = 0; ks < 2; ks++) {
            const int kcol = ks * 16;
            uint32_t ah[2][4], al[2][4];
            #pragma unroll
            for (int mi = 0; mi < 2; mi++) {
                int mrow = wr * 32 + mi * 16 + (lane & 15);
                int coff = kcol + ((lane >> 4) << 3);
                uint32_t byteoff = (uint32_t)(mrow * LDA + coff) * 2;
                ldsm4(ah[mi], sA0 + byteoff);
                ldsm4(al[mi], sA1 + byteoff);
            }
            uint32_t bh[2][4], blr[2][4];
            #pragma unroll
            for (int p = 0; p < 2; p++) {
                int nrow = wc * 32 + p * 16 + (lane & 7) + ((lane >> 4) << 3);
                int coff = kcol + (((lane >> 3) & 1) << 3);
                uint32_t byteoff = (uint32_t)(nrow * LDA + coff) * 2;
                ldsm4(bh[p],  sB0 + byteoff);
                ldsm4(blr[p], sB1 + byteoff);
            }
            #pragma unroll
            for (int mi = 0; mi < 2; mi++)
                #pragma unroll
                for (int p = 0; p < 2; p++)
                    #pragma unroll
                    for (int q = 0; q < 2; q++) {
                        float* d = acc[mi][p * 2 + q];
                        mma16816(d, ah[mi], bh[p][q * 2],  bh[p][q * 2 + 1]);
                        mma16816(d, ah[mi], blr[p][q * 2], blr[p][q * 2 + 1]);
                        mma16816(d, al[mi], bh[p][q * 2],  bh[p][q * 2 + 1]);
                    }
        }
        __syncthreads();
    }

    // ---- epilogue: bias + ELU -> bf16 split store ----
    #pragma unroll
    for (int mi = 0; mi < 2; mi++)
        #pragma unroll
        for (int nj = 0; nj < 4; nj++) {
            int r0 = rowBase + wr * 32 + mi * 16 + (lane >> 2);
            int c0 = colBase + wc * 32 + nj * 8 + 2 * (lane & 3);
            float b0 = bl[c0], b1 = bl[c0 + 1];
            #pragma unroll
            for (int half = 0; half < 2; half++) {
                int row = r0 + half * 8;
                if (row >= NN) continue;
                float v0 = acc[mi][nj][half * 2]     + b0;
                float v1 = acc[mi][nj][half * 2 + 1] + b1;
                v0 = (v0 > 0.f) ? v0 : expm1f(v0);
                v1 = (v1 > 0.f) ? v1 : expm1f(v1);
                __nv_bfloat16 h0 = __float2bfloat16(v0);
                __nv_bfloat16 h1 = __float2bfloat16(v1);
                __nv_bfloat16 l0 = __float2bfloat16(v0 - __bfloat162float(h0));
                __nv_bfloat16 l1 = __float2bfloat16(v1 - __bfloat162float(h1));
                *(uint32_t*)(g_hhi + (size_t)row * HID_DIM + c0) = pack2(h0, h1);
                *(uint32_t*)(g_hlo + (size_t)row * HID_DIM + c0) = pack2(l0, l1);
            }
        }
}

// ---------------- GEMM2 (HMMA): out = H @ W_out + b_out ----------------
// grid (391): BM=128, BN=64, K=256. Same skeleton; A is already bf16 split.
__global__ void __launch_bounds__(256) gemm2_mma(const float* __restrict__ bout,
                                                 float* __restrict__ out) {
    __shared__ __nv_bfloat16 sA[2][128 * LDA];
    __shared__ __nv_bfloat16 sB[2][64 * LDA];
    const int tid = threadIdx.x, lane = tid & 31, wid = tid >> 5;
    const int wr = wid & 3, wc = wid >> 2;
    const int rowBase = blockIdx.x * 128;
    const uint32_t sA0 = s2u(&sA[0][0]), sA1 = s2u(&sA[1][0]);
    const uint32_t sB0 = s2u(&sB[0][0]), sB1 = s2u(&sB[1][0]);

    float acc[2][4][4];
    #pragma unroll
    for (int i = 0; i < 2; i++)
        #pragma unroll
        for (int j = 0; j < 4; j++)
            #pragma unroll
            for (int q = 0; q < 4; q++) acc[i][j][q] = 0.f;

    const int arow = tid >> 1, aseg = tid & 1;
    const int grow = rowBase + arow;
    const bool okrow = grow < NN;
    const int bsplit = tid >> 7, bidx = tid & 127;
    const int brow = bidx >> 1, bseg = bidx & 1;
    const uint4 z4 = make_uint4(0, 0, 0, 0);

    for (int kc = 0; kc < 8; kc++) {
        // stage A (copy bf16 split)
        {
            const __nv_bfloat16* shp = g_hhi + (size_t)grow * HID_DIM + kc * 32 + aseg * 16;
            const __nv_bfloat16* slp = g_hlo + (size_t)grow * HID_DIM + kc * 32 + aseg * 16;
            __nv_bfloat16* dh = &sA[0][arow * LDA + aseg * 16];
            __nv_bfloat16* dl = &sA[1][arow * LDA + aseg * 16];
            *(uint4*)(dh)     = okrow ? *(const uint4*)(shp)     : z4;
            *(uint4*)(dh + 8) = okrow ? *(const uint4*)(shp + 8) : z4;
            *(uint4*)(dl)     = okrow ? *(const uint4*)(slp)     : z4;
            *(uint4*)(dl + 8) = okrow ? *(const uint4*)(slp + 8) : z4;
        }
        // stage B
        {
            const __nv_bfloat16* srcp = (bsplit == 0 ? g_B2hi : g_B2lo)
                + brow * 256 + kc * 32 + bseg * 16;
            __nv_bfloat16* dst = &sB[bsplit][brow * LDA + bseg * 16];
            *(uint4*)(dst)     = *(const uint4*)(srcp);
            *(uint4*)(dst + 8) = *(const uint4*)(srcp + 8);
        }
        __syncthreads();

        #pragma unroll
        for (int ks = 0; ks < 2; ks++) {
            const int kcol = ks * 16;
            uint32_t ah[2][4], al[2][4];
            #pragma unroll
            for (int mi = 0; mi < 2; mi++) {
                int mrow = wr * 32 + mi * 16 + (lane & 15);
                int coff = kcol + ((lane >> 4) << 3);
                uint32_t byteoff = (uint32_t)(mrow * LDA + coff) * 2;
                ldsm4(ah[mi], sA0 + byteoff);
                ldsm4(al[mi], sA1 + byteoff);
            }
            uint32_t bh[2][4], blr[2][4];
            #pragma unroll
            for (int p = 0; p < 2; p++) {
                int nrow = wc * 32 + p * 16 + (lane & 7) + ((lane >> 4) << 3);
                int coff = kcol + (((lane >> 3) & 1) << 3);
                uint32_t byteoff = (uint32_t)(nrow * LDA + coff) * 2;
                ldsm4(bh[p],  sB0 + byteoff);
                ldsm4(blr[p], sB1 + byteoff);
            }
            #pragma unroll
            for (int mi = 0; mi < 2; mi++)
                #pragma unroll
                for (int p = 0; p < 2; p++)
                    #pragma unroll
                    for (int q = 0; q < 2; q++) {
                        float* d = acc[mi][p * 2 + q];
                        mma16816(d, ah[mi], bh[p][q * 2],  bh[p][q * 2 + 1]);
                        mma16816(d, ah[mi], blr[p][q * 2], blr[p][q * 2 + 1]);
                        mma16816(d, al[mi], bh[p][q * 2],  bh[p][q * 2 + 1]);
                    }
        }
        __syncthreads();
    }

    // epilogue: + bias, fp32 float2 stores
    #pragma unroll
    for (int mi = 0; mi < 2; mi++)
        #pragma unroll
        for (int nj = 0; nj < 4; nj++) {
            int r0 = rowBase + wr * 32 + mi * 16 + (lane >> 2);
            int c0 = wc * 32 + nj * 8 + 2 * (lane & 3);
            float b0 = bout[c0], b1 = bout[c0 + 1];
            #pragma unroll
            for (int half = 0; half < 2; half++) {
                int row = r0 + half * 8;
                if (row >= NN) continue;
                float2 v = make_float2(acc[mi][nj][half * 2] + b0,
                                       acc[mi][nj][half * 2 + 1] + b1);
                *(float2*)(out + (size_t)row * OUT_DIM + c0) = v;
            }
        }
}

// ---------------- launch ----------------
extern "C" void kernel_launch(void* const* d_in, const int* in_sizes, int n_in,
                              void* d_out, int out_size) {
    const float* x    = (const float*)d_in[0];
    const void*  ei   = d_in[1];
    const float* Wl   = (const float*)d_in[2];
    const float* bl   = (const float*)d_in[3];
    const float* Wr   = (const float*)d_in[4];
    const float* Wout = (const float*)d_in[5];
    const float* bout = (const float*)d_in[6];
    float* out = (float*)d_out;

    setup_kernel<<<256, 256>>>((const unsigned int*)ei, Wl, Wr, Wout);
    convert_kernel<<<(NE + 255) / 256, 256>>>(ei);
    scan_kernel<<<SCAN_BLOCKS, 1024>>>();
    scatter_kernel<<<(NE + 255) / 256, 256>>>();
    agg_kernel<<<(NN * 32 + 255) / 256, 256>>>(x);

    dim3 g1(MTILES, 4);
    gemm1_mma<<<g1, 256>>>(x, bl);
    gemm2_mma<<<MTILES, 256>>>(bout, out);
}